// round 11
// baseline (speedup 1.0000x reference)
#include <cuda_runtime.h>
#include <cuda_bf16.h>
#include <cuda_fp16.h>
#include <cstdint>

#define BB 8
#define CC 256
#define NN 2048

// ---------------- scratch (device globals; no allocs) ----------------------
__device__ __nv_bfloat16 g_Xh[BB * NN * CC];                       // xT [b][n][c]
__device__ __nv_bfloat16 g_Wh[3 * CC * CC];                        // Wq,Wk,Wv bf16
__device__ __nv_bfloat16 g_Qh[BB * NN * CC];                       // [b][n][c]
__device__ __nv_bfloat16 g_Kh[BB * NN * CC];                       // [b][m][c]
__device__ __nv_bfloat16 g_Vh[BB * CC * NN];                       // [b][c][m]
__device__ __half        g_S [(size_t)BB * NN * NN];               // fp16 scores
__device__ __nv_bfloat16 g_Ph[(size_t)BB * NN * NN];               // probs (bf16)

// ---------------- PTX helpers (baseline PTX only) ---------------------------
__device__ __forceinline__ uint32_t smem_u32(const void* p) {
    uint32_t a;
    asm("{ .reg .u64 t; cvta.to.shared.u64 t, %1; cvt.u32.u64 %0, t; }"
        : "=r"(a) : "l"(p));
    return a;
}

#define CP_ASYNC16(dst, src) \
    asm volatile("cp.async.cg.shared.global [%0], [%1], 16;" \
                 :: "r"(dst), "l"(src) : "memory")
#define CP_COMMIT() asm volatile("cp.async.commit_group;" ::: "memory")
#define CP_WAIT(n)  asm volatile("cp.async.wait_group %0;" :: "n"(n) : "memory")

#define LDSM_X4(r0, r1, r2, r3, addr) \
    asm volatile("ldmatrix.sync.aligned.m8n8.x4.shared.b16 {%0,%1,%2,%3}, [%4];" \
                 : "=r"(r0), "=r"(r1), "=r"(r2), "=r"(r3) : "r"(addr))

#define MMA16816(c, a, b0, b1) \
    asm volatile("mma.sync.aligned.m16n8k16.row.col.f32.bf16.bf16.f32 " \
                 "{%0,%1,%2,%3}, {%4,%5,%6,%7}, {%8,%9}, {%0,%1,%2,%3};" \
                 : "+f"((c)[0]), "+f"((c)[1]), "+f"((c)[2]), "+f"((c)[3]) \
                 : "r"((a)[0]), "r"((a)[1]), "r"((a)[2]), "r"((a)[3]), \
                   "r"(b0), "r"(b1))

__device__ __forceinline__ __nv_bfloat16 bsplit_hi(float v) { return __float2bfloat16(v); }

#define ROW_STRIDE 80
#define TILE_BYTES 10240            // 128 rows * 80 B (one 32-col chunk-tile)
// gemm: BK=64 -> stage = [A0|B0|A1|B1], 2-stage ring
#define S_STAGE    (4 * TILE_BYTES)         // 40960
#define G_SMEM     (2 * S_STAGE)            // 81920
// qkv kernel smem: stage = A chunk (128 rows) + 3 W chunk tiles (64 rows)
#define QB_TILE    5120
#define QBUF       (TILE_BYTES + 3 * QB_TILE)   // 25600
#define QSMEM      (2 * QBUF)                   // 51200

// ---------------------------------------------------------------------------
// xsplit: x [b][c][n] fp32 -> xT [b][n][c] bf16
// ---------------------------------------------------------------------------
__global__ __launch_bounds__(256) void xsplit_kernel(const float* __restrict__ x)
{
    __shared__ float t[32][33];
    const int n0 = blockIdx.x * 32;
    const int c0 = blockIdx.y * 32;
    const int b  = blockIdx.z;
    const int tx = threadIdx.x & 31;
    const int ty = threadIdx.x >> 5;

    #pragma unroll
    for (int k = 0; k < 4; k++)
        t[ty + k * 8][tx] = x[((size_t)b * CC + c0 + ty + k * 8) * NN + n0 + tx];
    __syncthreads();
    #pragma unroll
    for (int k = 0; k < 4; k++) {
        const float v = t[tx][ty + k * 8];
        const size_t idx = ((size_t)b * NN + n0 + ty + k * 8) * CC + c0 + tx;
        g_Xh[idx] = bsplit_hi(v);
    }
}

// ---------------------------------------------------------------------------
// wsplit: Wq/Wk/Wv fp32 -> bf16
// ---------------------------------------------------------------------------
__global__ __launch_bounds__(256) void wsplit_kernel(
    const float* __restrict__ Wq, const float* __restrict__ Wk,
    const float* __restrict__ Wv)
{
    const int m = blockIdx.y;
    const int e = blockIdx.x * 256 + threadIdx.x;
    const float v = (m == 0 ? Wq : (m == 1 ? Wk : Wv))[e];
    g_Wh[m * CC * CC + e] = bsplit_hi(v);
}

// ---------------------------------------------------------------------------
// qkv_mma: single-pass bf16 HMMA projection, fused Q/K/V (proven R9 version).
// ---------------------------------------------------------------------------
__global__ __launch_bounds__(256) void qkv_mma(
    const float* __restrict__ bq, const float* __restrict__ bk,
    const float* __restrict__ bv)
{
    extern __shared__ __align__(16) char sm[];
    const int n0 = blockIdx.x * 128;
    const int o0 = blockIdx.y * 64;
    const int b  = blockIdx.z;

    const int tid  = threadIdx.x;
    const int wid  = tid >> 5;
    const int lane = tid & 31;
    const int wn   = wid & 1;
    const int wm   = wid >> 1;

    const uint32_t smbase = smem_u32(sm);

    const __nv_bfloat16* gX = g_Xh + ((size_t)b * NN + n0) * CC;
    const __nv_bfloat16* W3[3] = { g_Wh, g_Wh + CC * CC, g_Wh + 2 * CC * CC };

    const uint32_t offA = (uint32_t)((lane & 15) * ROW_STRIDE + (lane >> 4) * 16);
    const uint32_t offB = (uint32_t)(((lane & 7) + ((lane >> 4) << 3)) * ROW_STRIDE
                                     + (((lane >> 3) & 1) << 4));

    float acc[3][2][4][4] = {};

    const int alr = tid >> 1, alc = (tid & 1) * 2;
    const int brb = tid >> 2, bcb = tid & 3;

    auto issue = [&](int buf, int k0) {
        const uint32_t base = smbase + buf * QBUF;
        #pragma unroll
        for (int c = 0; c < 2; c++) {
            const int chunk = alc + c;
            CP_ASYNC16(base + (uint32_t)(alr * ROW_STRIDE + chunk * 16),
                       gX + (size_t)alr * CC + k0 + chunk * 8);
        }
        const uint32_t sob = base + TILE_BYTES
                           + (uint32_t)(brb * ROW_STRIDE + bcb * 16);
        const size_t gwb = (size_t)(o0 + brb) * CC + k0 + bcb * 8;
        #pragma unroll
        for (int m = 0; m < 3; m++)
            CP_ASYNC16(sob + m * QB_TILE, W3[m] + gwb);
        CP_COMMIT();
    };

    issue(0, 0);
    issue(1, 32);

    #pragma unroll 1
    for (int t = 0; t < 8; t++) {
        if (t == 7) { CP_WAIT(0); } else { CP_WAIT(1); }
        __syncthreads();
        const uint32_t base = smbase + (t & 1) * QBUF;

        #pragma unroll
        for (int ks = 0; ks < 2; ks++) {
            const uint32_t kb2 = ks * 32;
            uint32_t ah[2][4];
            #pragma unroll
            for (int mt = 0; mt < 2; mt++) {
                const uint32_t toff = (uint32_t)((wm * 32 + mt * 16) * ROW_STRIDE) + kb2 + offA;
                LDSM_X4(ah[mt][0], ah[mt][1], ah[mt][2], ah[mt][3], base + toff);
            }
            #pragma unroll
            for (int q = 0; q < 3; q++) {
                uint32_t bh[4][2];
                #pragma unroll
                for (int g = 0; g < 2; g++) {
                    const uint32_t toffb = (uint32_t)((wn * 32 + g * 16) * ROW_STRIDE) + kb2 + offB;
                    LDSM_X4(bh[2*g][0], bh[2*g][1], bh[2*g+1][0], bh[2*g+1][1],
                            base + TILE_BYTES + q * QB_TILE + toffb);
                }
                #pragma unroll
                for (int mt = 0; mt < 2; mt++)
                    #pragma unroll
                    for (int nt = 0; nt < 4; nt++)
                        MMA16816(acc[q][mt][nt], ah[mt], bh[nt][0], bh[nt][1]);
            }
        }
        __syncthreads();
        if (t + 2 < 8) issue(t & 1, (t + 2) * 32);
    }

    const int g  = lane >> 2;
    const int tq = lane & 3;

    // Q, K stores [n][c]
    #pragma unroll
    for (int mt = 0; mt < 2; mt++)
        #pragma unroll
        for (int h = 0; h < 2; h++) {
            const int n = n0 + wm * 32 + mt * 16 + g + h * 8;
            #pragma unroll
            for (int nt = 0; nt < 4; nt++) {
                const int col = o0 + wn * 32 + nt * 8 + tq * 2;
                const size_t idx = ((size_t)b * NN + n) * CC + col;
                const float q0 = acc[0][mt][nt][2*h]   + bq[col];
                const float q1 = acc[0][mt][nt][2*h+1] + bq[col + 1];
                const float k0v = acc[1][mt][nt][2*h]   + bk[col];
                const float k1v = acc[1][mt][nt][2*h+1] + bk[col + 1];
                *(__nv_bfloat162*)&g_Qh[idx] = __halves2bfloat162(bsplit_hi(q0), bsplit_hi(q1));
                *(__nv_bfloat162*)&g_Kh[idx] = __halves2bfloat162(bsplit_hi(k0v), bsplit_hi(k1v));
            }
        }

    // V: stage fp32 in smem, transpose to [c][n]
    __syncthreads();
    float* vbuf = (float*)sm;
    #pragma unroll
    for (int mt = 0; mt < 2; mt++)
        #pragma unroll
        for (int h = 0; h < 2; h++) {
            const int row = wm * 32 + mt * 16 + g + h * 8;
            #pragma unroll
            for (int nt = 0; nt < 4; nt++) {
                const int col = wn * 32 + nt * 8 + tq * 2;
                vbuf[row * 65 + col]     = acc[2][mt][nt][2*h]   + bv[o0 + col];
                vbuf[row * 65 + col + 1] = acc[2][mt][nt][2*h+1] + bv[o0 + col + 1];
            }
        }
    __syncthreads();
    #pragma unroll
    for (int cr = 0; cr < 8; cr++) {
        const int c = wid * 8 + cr;
        const size_t obase = ((size_t)b * CC + o0 + c) * NN + n0;
        #pragma unroll
        for (int it = 0; it < 2; it++) {
            const int nl = it * 64 + lane * 2;
            const float f0 = vbuf[nl * 65 + c];
            const float f1 = vbuf[(nl + 1) * 65 + c];
            *(__nv_bfloat162*)&g_Vh[obase + nl]
                = __halves2bfloat162(bsplit_hi(f0), bsplit_hi(f1));
        }
    }
}

// ---------------------------------------------------------------------------
// Single-pass bf16 NT GEMM, 128 threads (4 warps, 2x2), warp tile 64x64.
// BK=64 per barrier, 2-stage cp.async ring. 128 B smem per MMA (vs 192).
//   C[i][j] = s * sum_k A[i][k]*B[j][k]  (+ R[i][j])
// ---------------------------------------------------------------------------
template<int KTILES64, bool SCALE, bool RESID, typename TOUT>
__global__ __launch_bounds__(128, 2) void mma_gemm(
    const __nv_bfloat16* __restrict__ A, const __nv_bfloat16* __restrict__ B,
    TOUT* __restrict__ C, const float* __restrict__ R,
    int lda, int ldb, int ldc, float scale,
    size_t sA, size_t sB, size_t sC)
{
    extern __shared__ __align__(16) char sm[];

    const int j0 = blockIdx.x * 128;
    const int i0 = blockIdx.y * 128;
    const int b  = blockIdx.z;

    const int tid  = threadIdx.x;
    const int lane = tid & 31;
    const int wid  = tid >> 5;
    const int wm   = wid >> 1;        // 0..1
    const int wn   = wid & 1;         // 0..1

    const __nv_bfloat16* gA = A + (size_t)b * sA;
    const __nv_bfloat16* gB = B + (size_t)b * sB;

    const uint32_t smbase = smem_u32(sm);

    const uint32_t offA = (uint32_t)((lane & 15) * ROW_STRIDE + (lane >> 4) * 16);
    const uint32_t offB = (uint32_t)(((lane & 7) + ((lane >> 4) << 3)) * ROW_STRIDE
                                     + (((lane >> 3) & 1) << 4));

    float acc[4][8][4] = {};   // [mt 0..3][nt 0..7][reg]

    // cp.async: 128 threads, each owns one row of A and B; 4 granules x 2 chunks
    auto issue = [&](int buf, int k0) {
        const uint32_t base = smbase + buf * S_STAGE;
        #pragma unroll
        for (int cnk = 0; cnk < 2; cnk++) {
            const uint32_t cb = base + cnk * (2 * TILE_BYTES);
            #pragma unroll
            for (int c = 0; c < 4; c++) {
                const uint32_t so = cb + (uint32_t)(tid * ROW_STRIDE + c * 16);
                const int gk = k0 + cnk * 32 + c * 8;
                CP_ASYNC16(so,              gA + (size_t)(i0 + tid) * lda + gk);
                CP_ASYNC16(so + TILE_BYTES, gB + (size_t)(j0 + tid) * ldb + gk);
            }
        }
        CP_COMMIT();
    };

    issue(0, 0);
    issue(1, 64);

    #pragma unroll 1
    for (int t = 0; t < KTILES64; t++) {
        if (t == KTILES64 - 1) { CP_WAIT(0); } else { CP_WAIT(1); }
        __syncthreads();

        const uint32_t base = smbase + (t & 1) * S_STAGE;

        #pragma unroll
        for (int cnk = 0; cnk < 2; cnk++) {
            const uint32_t aA = base + cnk * (2 * TILE_BYTES);
            const uint32_t aB = aA + TILE_BYTES;
            #pragma unroll
            for (int ks = 0; ks < 2; ks++) {
                const uint32_t kb2 = ks * 32;
                uint32_t ahf[4][4];
                #pragma unroll
                for (int mt = 0; mt < 4; mt++) {
                    const uint32_t toff = (uint32_t)((wm * 64 + mt * 16) * ROW_STRIDE) + kb2 + offA;
                    LDSM_X4(ahf[mt][0], ahf[mt][1], ahf[mt][2], ahf[mt][3], aA + toff);
                }
                uint32_t bhf[8][2];
                #pragma unroll
                for (int g = 0; g < 4; g++) {
                    const uint32_t toff = (uint32_t)((wn * 64 + g * 16) * ROW_STRIDE) + kb2 + offB;
                    LDSM_X4(bhf[2*g][0], bhf[2*g][1], bhf[2*g+1][0], bhf[2*g+1][1], aB + toff);
                }
                #pragma unroll
                for (int mt = 0; mt < 4; mt++)
                    #pragma unroll
                    for (int nt = 0; nt < 8; nt++)
                        MMA16816(acc[mt][nt], ahf[mt], bhf[nt][0], bhf[nt][1]);
            }
        }

        __syncthreads();                 // all warps done reading buffer t&1
        if (t + 2 < KTILES64) issue(t & 1, (t + 2) * 64);
    }

    const int g  = lane >> 2;
    const int tq = lane & 3;
    TOUT* Cb = C + (size_t)b * sC;
    const float* Rb = R + (size_t)b * sC;

    #pragma unroll
    for (int mt = 0; mt < 4; mt++) {
        const int row0 = i0 + wm * 64 + mt * 16 + g;
        #pragma unroll
        for (int nt = 0; nt < 8; nt++) {
            const int col = j0 + wn * 64 + nt * 8 + tq * 2;
            float2 v0 = make_float2(acc[mt][nt][0], acc[mt][nt][1]);
            float2 v1 = make_float2(acc[mt][nt][2], acc[mt][nt][3]);
            if (SCALE) { v0.x *= scale; v0.y *= scale; v1.x *= scale; v1.y *= scale; }
            const size_t idx0 = (size_t)row0 * ldc + col;
            const size_t idx1 = (size_t)(row0 + 8) * ldc + col;
            if constexpr (RESID) {
                float2 r0 = *(const float2*)&Rb[idx0];
                float2 r1 = *(const float2*)&Rb[idx1];
                v0.x += r0.x; v0.y += r0.y; v1.x += r1.x; v1.y += r1.y;
            }
            if constexpr (sizeof(TOUT) == 2) {   // __half scores
                *(__half2*)&Cb[idx0] = __floats2half2_rn(v0.x, v0.y);
                *(__half2*)&Cb[idx1] = __floats2half2_rn(v1.x, v1.y);
            } else {                              // float out
                *(float2*)&Cb[idx0] = v0;
                *(float2*)&Cb[idx1] = v1;
            }
        }
    }
}

// ---------------------------------------------------------------------------
// softmax: fp16 scores -> bf16 probs. One uint4 load/store per thread.
// ---------------------------------------------------------------------------
__global__ __launch_bounds__(256) void softmax_kernel()
{
    __shared__ float redmax[8];
    __shared__ float redsum[8];

    const size_t row = blockIdx.x;
    const __half* p = g_S + row * NN;
    __nv_bfloat16* ph = g_Ph + row * NN;
    const int tid  = threadIdx.x;
    const int lane = tid & 31;
    const int warp = tid >> 5;

    uint4 raw = *(const uint4*)&p[tid * 8];
    const __half2* hp = (const __half2*)&raw;
    float v[8];
    #pragma unroll
    for (int q = 0; q < 4; q++) {
        float2 f = __half22float2(hp[q]);
        v[2*q] = f.x; v[2*q+1] = f.y;
    }

    float mx = -3.4e38f;
    #pragma unroll
    for (int t = 0; t < 8; t++) mx = fmaxf(mx, v[t]);
    #pragma unroll
    for (int o = 16; o > 0; o >>= 1)
        mx = fmaxf(mx, __shfl_xor_sync(0xffffffffu, mx, o));
    if (lane == 0) redmax[warp] = mx;
    __syncthreads();
    if (warp == 0) {
        float w = (lane < 8) ? redmax[lane] : -3.4e38f;
        #pragma unroll
        for (int o = 4; o > 0; o >>= 1)
            w = fmaxf(w, __shfl_xor_sync(0xffffffffu, w, o));
        if (lane == 0) redmax[0] = w;
    }
    __syncthreads();
    mx = redmax[0];

    float s = 0.0f;
    #pragma unroll
    for (int t = 0; t < 8; t++) {
        v[t] = __expf(v[t] - mx);
        s += v[t];
    }
    #pragma unroll
    for (int o = 16; o > 0; o >>= 1)
        s += __shfl_xor_sync(0xffffffffu, s, o);
    if (lane == 0) redsum[warp] = s;
    __syncthreads();
    if (warp == 0) {
        float w = (lane < 8) ? redsum[lane] : 0.0f;
        #pragma unroll
        for (int o = 4; o > 0; o >>= 1)
            w += __shfl_xor_sync(0xffffffffu, w, o);
        if (lane == 0) redsum[0] = w;
    }
    __syncthreads();
    const float inv = 1.0f / redsum[0];

    uint4 outw;
    __nv_bfloat162* op = (__nv_bfloat162*)&outw;
    #pragma unroll
    for (int q = 0; q < 4; q++)
        op[q] = __halves2bfloat162(bsplit_hi(v[2*q] * inv), bsplit_hi(v[2*q+1] * inv));
    *(uint4*)&ph[tid * 8] = outw;
}

// ---------------------------------------------------------------------------
extern "C" void kernel_launch(void* const* d_in, const int* in_sizes, int n_in,
                              void* d_out, int out_size)
{
    const float* x  = (const float*)d_in[0];
    const float* Wq = (const float*)d_in[1];
    const float* bq = (const float*)d_in[2];
    const float* Wk = (const float*)d_in[3];
    const float* bk = (const float*)d_in[4];
    const float* Wv = (const float*)d_in[5];
    const float* bv = (const float*)d_in[6];
    float* out = (float*)d_out;

    void *pQh, *pKh, *pVh, *pS, *pPh;
    cudaGetSymbolAddress(&pQh, g_Qh);
    cudaGetSymbolAddress(&pKh, g_Kh);
    cudaGetSymbolAddress(&pVh, g_Vh);
    cudaGetSymbolAddress(&pS,  g_S);
    cudaGetSymbolAddress(&pPh, g_Ph);

    cudaFuncSetAttribute(qkv_mma,
                         cudaFuncAttributeMaxDynamicSharedMemorySize, QSMEM);
    cudaFuncSetAttribute((const void*)mma_gemm<CC / 64, true, false, __half>,
                         cudaFuncAttributeMaxDynamicSharedMemorySize, G_SMEM);
    cudaFuncSetAttribute((const void*)mma_gemm<NN / 64, false, true, float>,
                         cudaFuncAttributeMaxDynamicSharedMemorySize, G_SMEM);

    xsplit_kernel<<<dim3(NN / 32, CC / 32, BB), 256>>>(x);
    wsplit_kernel<<<dim3(CC, 3), 256>>>(Wq, Wk, Wv);
    qkv_mma<<<dim3(NN / 128, CC / 64, BB), 256, QSMEM>>>(bq, bk, bv);

    // scores: S[n][m] = 1/16 * Q[n][:] . K[m][:]   (K=256) -> fp16
    mma_gemm<CC / 64, true, false, __half><<<dim3(NN / 128, NN / 128, BB), 128, G_SMEM>>>(
        (const __nv_bfloat16*)pQh, (const __nv_bfloat16*)pKh,
        (__half*)pS, nullptr,
        CC, CC, NN, 1.0f / 16.0f,
        (size_t)NN * CC, (size_t)NN * CC, (size_t)NN * NN);

    softmax_kernel<<<BB * NN, 256>>>();

    // out: C[c][n] = V[c][:] . P[n][:]  (K=2048) + x
    mma_gemm<NN / 64, false, true, float><<<dim3(NN / 128, CC / 128, BB), 128, G_SMEM>>>(
        (const __nv_bfloat16*)pVh, (const __nv_bfloat16*)pPh,
        out, x,
        NN, NN, NN, 1.0f,
        (size_t)CC * NN, (size_t)NN * NN, (size_t)CC * NN);
}

// round 12
// speedup vs baseline: 1.2166x; 1.2166x over previous
#include <cuda_runtime.h>
#include <cuda_bf16.h>
#include <cuda_fp16.h>
#include <cstdint>

#define BB 8
#define CC 256
#define NN 2048

// ---------------- scratch (device globals; no allocs) ----------------------
__device__ __nv_bfloat16 g_Xh[BB * NN * CC];                       // xT [b][n][c]
__device__ __nv_bfloat16 g_Wh[3 * CC * CC];                        // Wq,Wk,Wv bf16
__device__ __nv_bfloat16 g_Qh[BB * NN * CC];                       // [b][n][c]
__device__ __nv_bfloat16 g_Kh[BB * NN * CC];                       // [b][m][c]
__device__ __nv_bfloat16 g_Vh[BB * CC * NN];                       // [b][c][m]
__device__ __half        g_S [(size_t)BB * NN * NN];               // fp16 scores
__device__ __nv_bfloat16 g_Ph[(size_t)BB * NN * NN];               // probs (bf16)

// ---------------- PTX helpers (baseline PTX only) ---------------------------
__device__ __forceinline__ uint32_t smem_u32(const void* p) {
    uint32_t a;
    asm("{ .reg .u64 t; cvta.to.shared.u64 t, %1; cvt.u32.u64 %0, t; }"
        : "=r"(a) : "l"(p));
    return a;
}

#define CP_ASYNC16(dst, src) \
    asm volatile("cp.async.cg.shared.global [%0], [%1], 16;" \
                 :: "r"(dst), "l"(src) : "memory")
#define CP_COMMIT() asm volatile("cp.async.commit_group;" ::: "memory")
#define CP_WAIT(n)  asm volatile("cp.async.wait_group %0;" :: "n"(n) : "memory")

#define LDSM_X4(r0, r1, r2, r3, addr) \
    asm volatile("ldmatrix.sync.aligned.m8n8.x4.shared.b16 {%0,%1,%2,%3}, [%4];" \
                 : "=r"(r0), "=r"(r1), "=r"(r2), "=r"(r3) : "r"(addr))

#define MMA16816(c, a, b0, b1) \
    asm volatile("mma.sync.aligned.m16n8k16.row.col.f32.bf16.bf16.f32 " \
                 "{%0,%1,%2,%3}, {%4,%5,%6,%7}, {%8,%9}, {%0,%1,%2,%3};" \
                 : "+f"((c)[0]), "+f"((c)[1]), "+f"((c)[2]), "+f"((c)[3]) \
                 : "r"((a)[0]), "r"((a)[1]), "r"((a)[2]), "r"((a)[3]), \
                   "r"(b0), "r"(b1))

__device__ __forceinline__ __nv_bfloat16 bsplit_hi(float v) { return __float2bfloat16(v); }

#define ROW_STRIDE 80
#define TILE_BYTES 10240            // 128 rows * 80 B (one 32-col chunk-tile)
// gemm: BK=32, 3-stage ring, stage = [A|B]
#define S_STAGE    (2 * TILE_BYTES)         // 20480
#define G_SMEM     (3 * S_STAGE)            // 61440
// qkv kernel smem: stage = A chunk (128 rows) + 3 W chunk tiles (64 rows)
#define QB_TILE    5120
#define QBUF       (TILE_BYTES + 3 * QB_TILE)   // 25600
#define QSMEM      (2 * QBUF)                   // 51200

// ---------------------------------------------------------------------------
// xsplit: x [b][c][n] fp32 -> xT [b][n][c] bf16
// ---------------------------------------------------------------------------
__global__ __launch_bounds__(256) void xsplit_kernel(const float* __restrict__ x)
{
    __shared__ float t[32][33];
    const int n0 = blockIdx.x * 32;
    const int c0 = blockIdx.y * 32;
    const int b  = blockIdx.z;
    const int tx = threadIdx.x & 31;
    const int ty = threadIdx.x >> 5;

    #pragma unroll
    for (int k = 0; k < 4; k++)
        t[ty + k * 8][tx] = x[((size_t)b * CC + c0 + ty + k * 8) * NN + n0 + tx];
    __syncthreads();
    #pragma unroll
    for (int k = 0; k < 4; k++) {
        const float v = t[tx][ty + k * 8];
        const size_t idx = ((size_t)b * NN + n0 + ty + k * 8) * CC + c0 + tx;
        g_Xh[idx] = bsplit_hi(v);
    }
}

// ---------------------------------------------------------------------------
// wsplit: Wq/Wk/Wv fp32 -> bf16
// ---------------------------------------------------------------------------
__global__ __launch_bounds__(256) void wsplit_kernel(
    const float* __restrict__ Wq, const float* __restrict__ Wk,
    const float* __restrict__ Wv)
{
    const int m = blockIdx.y;
    const int e = blockIdx.x * 256 + threadIdx.x;
    const float v = (m == 0 ? Wq : (m == 1 ? Wk : Wv))[e];
    g_Wh[m * CC * CC + e] = bsplit_hi(v);
}

// ---------------------------------------------------------------------------
// qkv_mma: single-pass bf16 HMMA projection, fused Q/K/V (proven R9/R10).
// ---------------------------------------------------------------------------
__global__ __launch_bounds__(256) void qkv_mma(
    const float* __restrict__ bq, const float* __restrict__ bk,
    const float* __restrict__ bv)
{
    extern __shared__ __align__(16) char sm[];
    const int n0 = blockIdx.x * 128;
    const int o0 = blockIdx.y * 64;
    const int b  = blockIdx.z;

    const int tid  = threadIdx.x;
    const int wid  = tid >> 5;
    const int lane = tid & 31;
    const int wn   = wid & 1;
    const int wm   = wid >> 1;

    const uint32_t smbase = smem_u32(sm);

    const __nv_bfloat16* gX = g_Xh + ((size_t)b * NN + n0) * CC;
    const __nv_bfloat16* W3[3] = { g_Wh, g_Wh + CC * CC, g_Wh + 2 * CC * CC };

    const uint32_t offA = (uint32_t)((lane & 15) * ROW_STRIDE + (lane >> 4) * 16);
    const uint32_t offB = (uint32_t)(((lane & 7) + ((lane >> 4) << 3)) * ROW_STRIDE
                                     + (((lane >> 3) & 1) << 4));

    float acc[3][2][4][4] = {};

    const int alr = tid >> 1, alc = (tid & 1) * 2;
    const int brb = tid >> 2, bcb = tid & 3;

    auto issue = [&](int buf, int k0) {
        const uint32_t base = smbase + buf * QBUF;
        #pragma unroll
        for (int c = 0; c < 2; c++) {
            const int chunk = alc + c;
            CP_ASYNC16(base + (uint32_t)(alr * ROW_STRIDE + chunk * 16),
                       gX + (size_t)alr * CC + k0 + chunk * 8);
        }
        const uint32_t sob = base + TILE_BYTES
                           + (uint32_t)(brb * ROW_STRIDE + bcb * 16);
        const size_t gwb = (size_t)(o0 + brb) * CC + k0 + bcb * 8;
        #pragma unroll
        for (int m = 0; m < 3; m++)
            CP_ASYNC16(sob + m * QB_TILE, W3[m] + gwb);
        CP_COMMIT();
    };

    issue(0, 0);
    issue(1, 32);

    #pragma unroll 1
    for (int t = 0; t < 8; t++) {
        if (t == 7) { CP_WAIT(0); } else { CP_WAIT(1); }
        __syncthreads();
        const uint32_t base = smbase + (t & 1) * QBUF;

        #pragma unroll
        for (int ks = 0; ks < 2; ks++) {
            const uint32_t kb2 = ks * 32;
            uint32_t ah[2][4];
            #pragma unroll
            for (int mt = 0; mt < 2; mt++) {
                const uint32_t toff = (uint32_t)((wm * 32 + mt * 16) * ROW_STRIDE) + kb2 + offA;
                LDSM_X4(ah[mt][0], ah[mt][1], ah[mt][2], ah[mt][3], base + toff);
            }
            #pragma unroll
            for (int q = 0; q < 3; q++) {
                uint32_t bh[4][2];
                #pragma unroll
                for (int g = 0; g < 2; g++) {
                    const uint32_t toffb = (uint32_t)((wn * 32 + g * 16) * ROW_STRIDE) + kb2 + offB;
                    LDSM_X4(bh[2*g][0], bh[2*g][1], bh[2*g+1][0], bh[2*g+1][1],
                            base + TILE_BYTES + q * QB_TILE + toffb);
                }
                #pragma unroll
                for (int mt = 0; mt < 2; mt++)
                    #pragma unroll
                    for (int nt = 0; nt < 4; nt++)
                        MMA16816(acc[q][mt][nt], ah[mt], bh[nt][0], bh[nt][1]);
            }
        }
        __syncthreads();
        if (t + 2 < 8) issue(t & 1, (t + 2) * 32);
    }

    const int g  = lane >> 2;
    const int tq = lane & 3;

    // Q, K stores [n][c]
    #pragma unroll
    for (int mt = 0; mt < 2; mt++)
        #pragma unroll
        for (int h = 0; h < 2; h++) {
            const int n = n0 + wm * 32 + mt * 16 + g + h * 8;
            #pragma unroll
            for (int nt = 0; nt < 4; nt++) {
                const int col = o0 + wn * 32 + nt * 8 + tq * 2;
                const size_t idx = ((size_t)b * NN + n) * CC + col;
                const float q0 = acc[0][mt][nt][2*h]   + bq[col];
                const float q1 = acc[0][mt][nt][2*h+1] + bq[col + 1];
                const float k0v = acc[1][mt][nt][2*h]   + bk[col];
                const float k1v = acc[1][mt][nt][2*h+1] + bk[col + 1];
                *(__nv_bfloat162*)&g_Qh[idx] = __halves2bfloat162(bsplit_hi(q0), bsplit_hi(q1));
                *(__nv_bfloat162*)&g_Kh[idx] = __halves2bfloat162(bsplit_hi(k0v), bsplit_hi(k1v));
            }
        }

    // V: stage fp32 in smem, transpose to [c][n]
    __syncthreads();
    float* vbuf = (float*)sm;
    #pragma unroll
    for (int mt = 0; mt < 2; mt++)
        #pragma unroll
        for (int h = 0; h < 2; h++) {
            const int row = wm * 32 + mt * 16 + g + h * 8;
            #pragma unroll
            for (int nt = 0; nt < 4; nt++) {
                const int col = wn * 32 + nt * 8 + tq * 2;
                vbuf[row * 65 + col]     = acc[2][mt][nt][2*h]   + bv[o0 + col];
                vbuf[row * 65 + col + 1] = acc[2][mt][nt][2*h+1] + bv[o0 + col + 1];
            }
        }
    __syncthreads();
    #pragma unroll
    for (int cr = 0; cr < 8; cr++) {
        const int c = wid * 8 + cr;
        const size_t obase = ((size_t)b * CC + o0 + c) * NN + n0;
        #pragma unroll
        for (int it = 0; it < 2; it++) {
            const int nl = it * 64 + lane * 2;
            const float f0 = vbuf[nl * 65 + c];
            const float f1 = vbuf[(nl + 1) * 65 + c];
            *(__nv_bfloat162*)&g_Vh[obase + nl]
                = __halves2bfloat162(bsplit_hi(f0), bsplit_hi(f1));
        }
    }
}

// ---------------------------------------------------------------------------
// Single-pass bf16 NT GEMM — R7 pipeline shape (best measured):
// BK=32, 3-stage cp.async ring, 256 thr (8 warps 2x4), warp 64x32.
//   C[i][j] = s * sum_k A[i][k]*B[j][k]  (+ R[i][j]) ; TOUT = __half or float.
// Prefetch into buf+2 right after the front barrier: with 3 stages,
// buf+2 != buf (being read) and != buf+1 (already loaded) — no hazard.
// ---------------------------------------------------------------------------
template<int KTILES, bool SCALE, bool RESID, typename TOUT>
__global__ __launch_bounds__(256, 2) void mma_gemm(
    const __nv_bfloat16* __restrict__ A, const __nv_bfloat16* __restrict__ B,
    TOUT* __restrict__ C, const float* __restrict__ R,
    int lda, int ldb, int ldc, float scale,
    size_t sA, size_t sB, size_t sC)
{
    extern __shared__ __align__(16) char sm[];

    const int j0 = blockIdx.x * 128;
    const int i0 = blockIdx.y * 128;
    const int b  = blockIdx.z;

    const int tid  = threadIdx.x;
    const int lane = tid & 31;
    const int wid  = tid >> 5;
    const int wm   = wid >> 2;
    const int wn   = wid & 3;

    const __nv_bfloat16* gA = A + (size_t)b * sA;
    const __nv_bfloat16* gB = B + (size_t)b * sB;

    const int lr = tid >> 1;
    const int lc = (tid & 1) * 2;
    const uint32_t smbase = smem_u32(sm);

    const uint32_t offA = (uint32_t)((lane & 15) * ROW_STRIDE + (lane >> 4) * 16);
    const uint32_t offB = (uint32_t)(((lane & 7) + ((lane >> 4) << 3)) * ROW_STRIDE
                                     + (((lane >> 3) & 1) << 4));

    float acc[4][4][4] = {};

    auto issue = [&](int buf, int k0) {
        const uint32_t base = smbase + buf * S_STAGE;
        #pragma unroll
        for (int c = 0; c < 2; c++) {
            const int chunk = lc + c;
            const uint32_t so = base + (uint32_t)(lr * ROW_STRIDE + chunk * 16);
            CP_ASYNC16(so,              gA + (size_t)(i0 + lr) * lda + k0 + chunk * 8);
            CP_ASYNC16(so + TILE_BYTES, gB + (size_t)(j0 + lr) * ldb + k0 + chunk * 8);
        }
        CP_COMMIT();
    };

    issue(0, 0);
    issue(1, 32);

    int buf = 0;
    #pragma unroll 1
    for (int t = 0; t < KTILES; t++) {
        if (t == KTILES - 1) { CP_WAIT(0); } else { CP_WAIT(1); }
        __syncthreads();
        if (t + 2 < KTILES) {
            int pb = buf + 2; if (pb >= 3) pb -= 3;
            issue(pb, (t + 2) * 32);
        }

        const uint32_t aA = smbase + buf * S_STAGE;
        const uint32_t aB = aA + TILE_BYTES;

        #pragma unroll
        for (int ks = 0; ks < 2; ks++) {
            const uint32_t kb2 = ks * 32;
            uint32_t ahf[4][4];
            #pragma unroll
            for (int mt = 0; mt < 4; mt++) {
                const uint32_t toff = (uint32_t)((wm * 64 + mt * 16) * ROW_STRIDE) + kb2 + offA;
                LDSM_X4(ahf[mt][0], ahf[mt][1], ahf[mt][2], ahf[mt][3], aA + toff);
            }
            uint32_t bhf[4][2];
            #pragma unroll
            for (int g = 0; g < 2; g++) {
                const uint32_t toff = (uint32_t)((wn * 32 + g * 16) * ROW_STRIDE) + kb2 + offB;
                LDSM_X4(bhf[2*g][0], bhf[2*g][1], bhf[2*g+1][0], bhf[2*g+1][1], aB + toff);
            }
            #pragma unroll
            for (int mt = 0; mt < 4; mt++)
                #pragma unroll
                for (int nt = 0; nt < 4; nt++)
                    MMA16816(acc[mt][nt], ahf[mt], bhf[nt][0], bhf[nt][1]);
        }

        buf = (buf + 1 == 3) ? 0 : buf + 1;
    }

    const int g  = lane >> 2;
    const int tq = lane & 3;
    TOUT* Cb = C + (size_t)b * sC;
    const float* Rb = R + (size_t)b * sC;

    #pragma unroll
    for (int mt = 0; mt < 4; mt++) {
        const int row0 = i0 + wm * 64 + mt * 16 + g;
        #pragma unroll
        for (int nt = 0; nt < 4; nt++) {
            const int col = j0 + wn * 32 + nt * 8 + tq * 2;
            float2 v0 = make_float2(acc[mt][nt][0], acc[mt][nt][1]);
            float2 v1 = make_float2(acc[mt][nt][2], acc[mt][nt][3]);
            if (SCALE) { v0.x *= scale; v0.y *= scale; v1.x *= scale; v1.y *= scale; }
            const size_t idx0 = (size_t)row0 * ldc + col;
            const size_t idx1 = (size_t)(row0 + 8) * ldc + col;
            if constexpr (RESID) {
                float2 r0 = *(const float2*)&Rb[idx0];
                float2 r1 = *(const float2*)&Rb[idx1];
                v0.x += r0.x; v0.y += r0.y; v1.x += r1.x; v1.y += r1.y;
            }
            if constexpr (sizeof(TOUT) == 2) {   // __half scores
                *(__half2*)&Cb[idx0] = __floats2half2_rn(v0.x, v0.y);
                *(__half2*)&Cb[idx1] = __floats2half2_rn(v1.x, v1.y);
            } else {                              // float out
                *(float2*)&Cb[idx0] = v0;
                *(float2*)&Cb[idx1] = v1;
            }
        }
    }
}

// ---------------------------------------------------------------------------
// softmax: fp16 scores -> bf16 probs. One uint4 load/store per thread.
// ---------------------------------------------------------------------------
__global__ __launch_bounds__(256) void softmax_kernel()
{
    __shared__ float redmax[8];
    __shared__ float redsum[8];

    const size_t row = blockIdx.x;
    const __half* p = g_S + row * NN;
    __nv_bfloat16* ph = g_Ph + row * NN;
    const int tid  = threadIdx.x;
    const int lane = tid & 31;
    const int warp = tid >> 5;

    uint4 raw = *(const uint4*)&p[tid * 8];
    const __half2* hp = (const __half2*)&raw;
    float v[8];
    #pragma unroll
    for (int q = 0; q < 4; q++) {
        float2 f = __half22float2(hp[q]);
        v[2*q] = f.x; v[2*q+1] = f.y;
    }

    float mx = -3.4e38f;
    #pragma unroll
    for (int t = 0; t < 8; t++) mx = fmaxf(mx, v[t]);
    #pragma unroll
    for (int o = 16; o > 0; o >>= 1)
        mx = fmaxf(mx, __shfl_xor_sync(0xffffffffu, mx, o));
    if (lane == 0) redmax[warp] = mx;
    __syncthreads();
    if (warp == 0) {
        float w = (lane < 8) ? redmax[lane] : -3.4e38f;
        #pragma unroll
        for (int o = 4; o > 0; o >>= 1)
            w = fmaxf(w, __shfl_xor_sync(0xffffffffu, w, o));
        if (lane == 0) redmax[0] = w;
    }
    __syncthreads();
    mx = redmax[0];

    float s = 0.0f;
    #pragma unroll
    for (int t = 0; t < 8; t++) {
        v[t] = __expf(v[t] - mx);
        s += v[t];
    }
    #pragma unroll
    for (int o = 16; o > 0; o >>= 1)
        s += __shfl_xor_sync(0xffffffffu, s, o);
    if (lane == 0) redsum[warp] = s;
    __syncthreads();
    if (warp == 0) {
        float w = (lane < 8) ? redsum[lane] : 0.0f;
        #pragma unroll
        for (int o = 4; o > 0; o >>= 1)
            w += __shfl_xor_sync(0xffffffffu, w, o);
        if (lane == 0) redsum[0] = w;
    }
    __syncthreads();
    const float inv = 1.0f / redsum[0];

    uint4 outw;
    __nv_bfloat162* op = (__nv_bfloat162*)&outw;
    #pragma unroll
    for (int q = 0; q < 4; q++)
        op[q] = __halves2bfloat162(bsplit_hi(v[2*q] * inv), bsplit_hi(v[2*q+1] * inv));
    *(uint4*)&ph[tid * 8] = outw;
}

// ---------------------------------------------------------------------------
extern "C" void kernel_launch(void* const* d_in, const int* in_sizes, int n_in,
                              void* d_out, int out_size)
{
    const float* x  = (const float*)d_in[0];
    const float* Wq = (const float*)d_in[1];
    const float* bq = (const float*)d_in[2];
    const float* Wk = (const float*)d_in[3];
    const float* bk = (const float*)d_in[4];
    const float* Wv = (const float*)d_in[5];
    const float* bv = (const float*)d_in[6];
    float* out = (float*)d_out;

    void *pQh, *pKh, *pVh, *pS, *pPh;
    cudaGetSymbolAddress(&pQh, g_Qh);
    cudaGetSymbolAddress(&pKh, g_Kh);
    cudaGetSymbolAddress(&pVh, g_Vh);
    cudaGetSymbolAddress(&pS,  g_S);
    cudaGetSymbolAddress(&pPh, g_Ph);

    cudaFuncSetAttribute(qkv_mma,
                         cudaFuncAttributeMaxDynamicSharedMemorySize, QSMEM);
    cudaFuncSetAttribute((const void*)mma_gemm<CC / 32, true, false, __half>,
                         cudaFuncAttributeMaxDynamicSharedMemorySize, G_SMEM);
    cudaFuncSetAttribute((const void*)mma_gemm<NN / 32, false, true, float>,
                         cudaFuncAttributeMaxDynamicSharedMemorySize, G_SMEM);

    xsplit_kernel<<<dim3(NN / 32, CC / 32, BB), 256>>>(x);
    wsplit_kernel<<<dim3(CC, 3), 256>>>(Wq, Wk, Wv);
    qkv_mma<<<dim3(NN / 128, CC / 64, BB), 256, QSMEM>>>(bq, bk, bv);

    // scores: S[n][m] = 1/16 * Q[n][:] . K[m][:]   (K=256) -> fp16
    mma_gemm<CC / 32, true, false, __half><<<dim3(NN / 128, NN / 128, BB), 256, G_SMEM>>>(
        (const __nv_bfloat16*)pQh, (const __nv_bfloat16*)pKh,
        (__half*)pS, nullptr,
        CC, CC, NN, 1.0f / 16.0f,
        (size_t)NN * CC, (size_t)NN * CC, (size_t)NN * NN);

    softmax_kernel<<<BB * NN, 256>>>();

    // out: C[c][n] = V[c][:] . P[n][:]  (K=2048) + x
    mma_gemm<NN / 32, false, true, float><<<dim3(NN / 128, CC / 128, BB), 256, G_SMEM>>>(
        (const __nv_bfloat16*)pVh, (const __nv_bfloat16*)pPh,
        out, x,
        NN, NN, NN, 1.0f,
        (size_t)CC * NN, (size_t)NN * NN, (size_t)CC * NN);
}